// round 15
// baseline (speedup 1.0000x reference)
#include <cuda_runtime.h>
#include <cuda_fp16.h>
#include <math.h>

#define NMAX 100000
#define EMAX 1310720
#define DD 64

// -------- persistent scratch (device globals; no allocation allowed) --------
__device__ __align__(16) __half g_Ph[NMAX * 32];     // x @ Wp1[:64]
__device__ __align__(16) __half g_Qh[NMAX * 32];     // x @ Wn1[:64]
__device__ __align__(16) __half g_RSh[NMAX * 64];    // [x@Wp1[64:]+bp1 | x@Wn1[64:]+bn1]
__device__ __align__(16) __half g_accPh[NMAX * 32];  // zeroed by node1e after read
__device__ __align__(16) __half g_accNh[NMAX * 32];  // zeroed by node1e after read
__device__ __align__(16) __half g_xpnh[NMAX * 64];   // [xp | xn] (fully overwritten)
__device__ __align__(16) __half g_accP2h[NMAX * 64]; // zeroed by node2TC after read
__device__ __align__(16) __half g_accN2h[NMAX * 64]; // zeroed by node2TC after read
__device__ __align__(16) float  g_cntp[NMAX];        // zeroed by node2TC after read
__device__ __align__(16) float  g_cntn[NMAX];
__device__ __align__(16) int2   g_es[EMAX];          // {src, dst or ~dst(neg)}

// ------------------------------ tiny helpers --------------------------------
__device__ __forceinline__ void red_v4h(__half* p, uint4 v) {
    asm volatile("red.global.add.noftz.v4.f16x2 [%0], {%1,%2,%3,%4};"
                 :: "l"(p), "r"(v.x), "r"(v.y), "r"(v.z), "r"(v.w)
                 : "memory");
}
__device__ __forceinline__ unsigned packh2(float a, float b) {
    __half2 h = __floats2half2_rn(a, b);
    return *(unsigned*)&h;
}
__device__ __forceinline__ void h8tof(uint4 v, float* o) {
    const __half2* h = (const __half2*)&v;
#pragma unroll
    for (int j = 0; j < 4; j++) {
        float2 f = __half22float2(h[j]);
        o[2 * j] = f.x;
        o[2 * j + 1] = f.y;
    }
}
// fast tanh: 1 - 2/(exp(2x)+1); inf-safe at both ends, rel err ~1e-6
__device__ __forceinline__ float ftanh(float x) {
    float e = __expf(2.0f * x);
    return 1.0f - __fdividef(2.0f, e + 1.0f);
}

// ---------------- mma.m16n8k16 f16 -> f32, analytic fragments ---------------
__device__ __forceinline__ void mma16816(float* c, const unsigned* a, const unsigned* b) {
    asm volatile(
        "mma.sync.aligned.m16n8k16.row.col.f32.f16.f16.f32 "
        "{%0,%1,%2,%3}, {%4,%5,%6,%7}, {%8,%9}, {%0,%1,%2,%3};"
        : "+f"(c[0]), "+f"(c[1]), "+f"(c[2]), "+f"(c[3])
        : "r"(a[0]), "r"(a[1]), "r"(a[2]), "r"(a[3]), "r"(b[0]), "r"(b[1]));
}
__device__ __forceinline__ void lda(unsigned* a, const __half* base, int stride,
                                    int k0, int lane) {
    int gr = lane >> 2, gc = lane & 3;
    const __half* p = base + gr * stride + k0 + 2 * gc;
    a[0] = *(const unsigned*)p;
    a[1] = *(const unsigned*)(p + 8 * stride);
    a[2] = *(const unsigned*)(p + 8);
    a[3] = *(const unsigned*)(p + 8 * stride + 8);
}
__device__ __forceinline__ void ldb(unsigned* b, const __half* WT, int stride,
                                    int n0, int k0, int lane) {
    int gn = lane >> 2, gc = lane & 3;
    const __half* p = WT + (n0 + gn) * stride + k0 + 2 * gc;
    b[0] = *(const unsigned*)p;
    b[1] = *(const unsigned*)(p + 8);
}
// loop1 A-operand element pair straight from gmem (see R12 comments)
__device__ __forceinline__ unsigned ldA96(int n, int ka, int off,
                                          __half2 ivp, __half2 ivn) {
    __half2 v;
    if (ka < 32) {
        v = *(const __half2*)(g_accP2h + (size_t)n * 64 + off + ka);
        v = __hmul2(v, ivp);
    } else if (ka < 64) {
        v = *(const __half2*)(g_accN2h + (size_t)n * 64 + off + (ka - 32));
        v = __hmul2(v, ivn);
    } else {
        v = *(const __half2*)(g_xpnh + (size_t)n * 64 + off + (ka - 64));
    }
    return *(unsigned*)&v;
}

// ---------- fused init + projection: EVERY block does proj then pack --------
// (proj and edge-pack are independent; interleaving them in one exactly-
//  resident wave removes the two-wave serialization seen in R13's profile)
__global__ void __launch_bounds__(256)
k_initproj(const float* __restrict__ x,
           const float* __restrict__ Wp1, const float* __restrict__ bp1,
           const float* __restrict__ Wn1, const float* __restrict__ bn1,
           const int* __restrict__ ei, int E, int n_nodes, int n_tiles) {
    __shared__ __align__(16) __half WT[128 * 72];
    __shared__ float b1s[64];
    int tid = threadIdx.x;
    for (int i = tid; i < 64 * 128; i += 256) {
        int k = i >> 7, col = i & 127;
        float w;
        if (col < 32)       w = Wp1[k * 32 + col];
        else if (col < 64)  w = Wn1[k * 32 + (col - 32)];
        else if (col < 96)  w = Wp1[(64 + k) * 32 + (col - 64)];
        else                w = Wn1[(64 + k) * 32 + (col - 96)];
        WT[col * 72 + k] = __float2half(w);
    }
    if (tid < 32) { b1s[tid] = bp1[tid]; b1s[32 + tid] = bn1[tid]; }
    __syncthreads();

    int wid = tid >> 5, lane = tid & 31;
    int gr = lane >> 2, gc = lane & 3;
    int tile_stride = gridDim.x * 8;

    // ---------------- projection GEMM, grid-stride over tiles ---------------
    for (int tile = blockIdx.x * 8 + wid; tile < n_tiles; tile += tile_stride) {
        int base = tile * 16;
        int r0 = base + gr, r1 = base + gr + 8;
        bool v0 = r0 < n_nodes, v1 = r1 < n_nodes;
        size_t rr0 = v0 ? (size_t)r0 : 0, rr1 = v1 ? (size_t)r1 : 0;

        unsigned af[16];
#pragma unroll
        for (int kc = 0; kc < 4; kc++) {
            const float* p0 = x + rr0 * 64 + 16 * kc + 2 * gc;
            const float* p1 = x + rr1 * 64 + 16 * kc + 2 * gc;
            float2 f0 = *(const float2*)p0;
            float2 f1 = *(const float2*)p1;
            float2 f2 = *(const float2*)(p0 + 8);
            float2 f3 = *(const float2*)(p1 + 8);
            af[4 * kc]     = packh2(f0.x, f0.y);
            af[4 * kc + 1] = packh2(f1.x, f1.y);
            af[4 * kc + 2] = packh2(f2.x, f2.y);
            af[4 * kc + 3] = packh2(f3.x, f3.y);
        }

        float c[16][4];
#pragma unroll
        for (int t = 0; t < 16; t++)
            c[t][0] = c[t][1] = c[t][2] = c[t][3] = 0.f;
#pragma unroll
        for (int kc = 0; kc < 4; kc++) {
#pragma unroll
            for (int t = 0; t < 16; t++) {
                unsigned b[2];
                ldb(b, WT, 72, 8 * t, 16 * kc, lane);
                mma16816(c[t], af + 4 * kc, b);
            }
        }
#pragma unroll
        for (int t = 0; t < 16; t++) {
            int colw = 8 * t + 2 * gc;
            if (colw < 64) {
                __half* dstb = (colw < 32) ? g_Ph : g_Qh;
                int cw = colw & 31;
                if (v0) *(unsigned*)(dstb + rr0 * 32 + cw) = packh2(c[t][0], c[t][1]);
                if (v1) *(unsigned*)(dstb + rr1 * 32 + cw) = packh2(c[t][2], c[t][3]);
            } else {
                float bb0 = b1s[colw - 64], bb1 = b1s[colw - 63];
                if (v0) *(unsigned*)(g_RSh + rr0 * 64 + (colw - 64)) =
                    packh2(c[t][0] + bb0, c[t][1] + bb1);
                if (v1) *(unsigned*)(g_RSh + rr1 * 64 + (colw - 64)) =
                    packh2(c[t][2] + bb0, c[t][3] + bb1);
            }
        }
    }

    // ---------------- edge pack + degree counts, grid-stride ----------------
    {
        int i = blockIdx.x * 256 + tid;
        int stride = gridDim.x * 256;
        for (int e = i; e < E; e += stride) {
            long eb = 3L * e;
            int s  = __ldg(ei + eb);
            int d  = __ldg(ei + eb + 1);
            int sg = __ldg(ei + eb + 2);
            bool pos = (sg > 0);
            g_es[e] = make_int2(s, pos ? d : ~d);
            atomicAdd(pos ? (g_cntp + d) : (g_cntn + d), 1.0f);
        }
    }
}

// --------------------------- layer-1 aggregation ----------------------------
// 2 edges per thread; 4 chunk-threads per edge pair. (counts done in init)
__global__ void k_edge1(int npairs, int E) {
    long idx = (long)blockIdx.x * blockDim.x + threadIdx.x;
    int p = (int)(idx >> 2);
    if (p >= npairs) return;
    int c = (int)(idx & 3);
    int4 es = __ldg((const int4*)g_es + p);
    bool has1 = (2 * p + 1 < E);

    int s0 = es.x, d0 = es.y;
    bool pos0 = (d0 >= 0);
    if (!pos0) d0 = ~d0;
    int s1 = es.z, d1 = es.w;
    bool pos1 = (d1 >= 0);
    if (!pos1) d1 = ~d1;

    uint4 v0 = *((const uint4*)(pos0 ? g_Ph : g_Qh) + (size_t)s0 * 4 + c);
    uint4 v1;
    if (has1) v1 = *((const uint4*)(pos1 ? g_Ph : g_Qh) + (size_t)s1 * 4 + c);

    red_v4h((pos0 ? g_accPh : g_accNh) + (size_t)d0 * 32 + c * 8, v0);
    if (has1)
        red_v4h((pos1 ? g_accPh : g_accNh) + (size_t)d1 * 32 + c * 8, v1);
}

// --------------- node layer 1: elementwise tanh + acc re-zero ---------------
__global__ void k_node1e(long total) {
    long idx = (long)blockIdx.x * blockDim.x + threadIdx.x;
    if (idx >= total) return;
    int n = (int)(idx >> 3);
    int c = (int)(idx & 7);
    uint4 rs = ((const uint4*)g_RSh)[idx];
    uint4 z4 = make_uint4(0u, 0u, 0u, 0u);
    uint4 acc;
    float inv;
    if (c < 4) {
        acc = ((const uint4*)g_accPh)[(size_t)n * 4 + c];
        ((uint4*)g_accPh)[(size_t)n * 4 + c] = z4;   // re-zero for next launch
        inv = 1.0f / fmaxf(g_cntp[n], 1.0f);
    } else {
        acc = ((const uint4*)g_accNh)[(size_t)n * 4 + (c - 4)];
        ((uint4*)g_accNh)[(size_t)n * 4 + (c - 4)] = z4;
        inv = 1.0f / fmaxf(g_cntn[n], 1.0f);
    }
    float rf[8], af[8];
    h8tof(rs, rf);
    h8tof(acc, af);
    uint4 o;
    unsigned* ou = (unsigned*)&o;
#pragma unroll
    for (int j = 0; j < 4; j++)
        ou[j] = packh2(ftanh(rf[2 * j] + af[2 * j] * inv),
                       ftanh(rf[2 * j + 1] + af[2 * j + 1] * inv));
    ((uint4*)g_xpnh)[idx] = o;
}

// --------------------------- layer-2 aggregation ----------------------------
// 2 edges per thread; 8 chunk-threads per edge pair.
__global__ void k_edge2(int npairs, int E) {
    long idx = (long)blockIdx.x * blockDim.x + threadIdx.x;
    int p = (int)(idx >> 3);
    if (p >= npairs) return;
    int c = (int)(idx & 7);
    int4 es = __ldg((const int4*)g_es + p);
    bool has1 = (2 * p + 1 < E);

    int s0 = es.x, d0 = es.y;
    int s1 = es.z, d1 = es.w;

    uint4 v0 = *((const uint4*)g_xpnh + (size_t)s0 * 8 + c);
    uint4 v1;
    if (has1) v1 = *((const uint4*)g_xpnh + (size_t)s1 * 8 + c);

    if (d0 >= 0) {
        red_v4h(g_accP2h + (size_t)d0 * 64 + c * 8, v0);
    } else {
        red_v4h(g_accN2h + (size_t)(~d0) * 64 + (((c + 4) & 7)) * 8, v0);
    }
    if (has1) {
        if (d1 >= 0) {
            red_v4h(g_accP2h + (size_t)d1 * 64 + c * 8, v1);
        } else {
            red_v4h(g_accN2h + (size_t)(~d1) * 64 + (((c + 4) & 7)) * 8, v1);
        }
    }
}

// ------------- node layer 2 + MLP head: tensor-core warp tiles --------------
// grid-stride tiles; loop1 A register-prefetched; accs+counts re-zeroed here.
__global__ void __launch_bounds__(256, 2)
k_node2TC(const float* __restrict__ Wp2, const float* __restrict__ bp2,
          const float* __restrict__ Wn2, const float* __restrict__ bn2,
          const float* __restrict__ Ww,  const float* __restrict__ bw,
          const float* __restrict__ Wm1, const float* __restrict__ bm1,
          const float* __restrict__ g1,  const float* __restrict__ be1,
          const float* __restrict__ rm1, const float* __restrict__ rv1,
          const float* __restrict__ Wm2, const float* __restrict__ bm2,
          const float* __restrict__ g2,  const float* __restrict__ be2,
          const float* __restrict__ rm2, const float* __restrict__ rv2,
          const float* __restrict__ Wm3, const float* __restrict__ bm3,
          float* __restrict__ outz, float* __restrict__ outp,
          int n_nodes, int n_tiles) {
    extern __shared__ __align__(16) __half smh[];
    __half* WpT = smh;                    // 32 x 104
    __half* WnT = smh + 3328;             // 32 x 104
    __half* WwT = smh + 6656;             // 64 x 72
    __half* W1T = smh + 11264;            // 64 x 72
    __half* W2T = smh + 15872;            // 64 x 72
    float* fb = (float*)(smh + 29696);
    float* bp2s = fb;         // 32
    float* bn2s = fb + 32;    // 32
    float* bws  = fb + 64;    // 64
    float* sc1  = fb + 128;   // 64
    float* of1  = fb + 192;   // 64
    float* sc2  = fb + 256;   // 64
    float* of2  = fb + 320;   // 64
    float* w3s  = fb + 384;   // 64
    // fb[448] = b3

    int tid = threadIdx.x;
    for (int i = tid; i < 96 * 32; i += 256) {
        int k = i >> 5, nn = i & 31;
        WpT[nn * 104 + k] = __float2half(Wp2[i]);
        WnT[nn * 104 + k] = __float2half(Wn2[i]);
    }
    for (int i = tid; i < 64 * 64; i += 256) {
        int k = i >> 6, nn = i & 63;
        WwT[nn * 72 + k] = __float2half(Ww[i]);
        W1T[nn * 72 + k] = __float2half(Wm1[i]);
        W2T[nn * 72 + k] = __float2half(Wm2[i]);
    }
    if (tid < 32) { bp2s[tid] = bp2[tid]; bn2s[tid] = bn2[tid]; }
    if (tid < 64) {
        bws[tid] = bw[tid];
        float s1 = g1[tid] * rsqrtf(rv1[tid] + 1e-5f);
        sc1[tid] = s1;
        of1[tid] = (bm1[tid] - rm1[tid]) * s1 + be1[tid];
        float s2 = g2[tid] * rsqrtf(rv2[tid] + 1e-5f);
        sc2[tid] = s2;
        of2[tid] = (bm2[tid] - rm2[tid]) * s2 + be2[tid];
        w3s[tid] = Wm3[tid];
    }
    if (tid == 0) fb[448] = bm3[0];
    __syncthreads();

    int wid = tid >> 5, lane = tid & 31;
    __half* zs = smh + 20480 + wid * 1152;  // 16 x 72
    int gr = lane >> 2, gc = lane & 3;
    int tile_stride = gridDim.x * 8;

    for (int tile = blockIdx.x * 8 + wid; tile < n_tiles; tile += tile_stride) {
        int base = tile * 16;
        int nr0 = base + gr, nr1 = base + gr + 8;
        bool v0 = nr0 < n_nodes, v1 = nr1 < n_nodes;
        int n0 = v0 ? nr0 : (n_nodes - 1);
        int n1 = v1 ? nr1 : (n_nodes - 1);

        __half2 ivp0 = __float2half2_rn(1.0f / fmaxf(g_cntp[n0], 1.0f));
        __half2 ivn0 = __float2half2_rn(1.0f / fmaxf(g_cntn[n0], 1.0f));
        __half2 ivp1 = __float2half2_rn(1.0f / fmaxf(g_cntp[n1], 1.0f));
        __half2 ivn1 = __float2half2_rn(1.0f / fmaxf(g_cntn[n1], 1.0f));

        // ---- loop1 prefetch: ALL 48 A-fragment words issued before any mma
        unsigned ap[24], an[24];
#pragma unroll
        for (int kc = 0; kc < 6; kc++) {
            int ka = 16 * kc + 2 * gc;
            ap[4 * kc]     = ldA96(n0, ka, 0, ivp0, ivn0);
            ap[4 * kc + 1] = ldA96(n1, ka, 0, ivp1, ivn1);
            ap[4 * kc + 2] = ldA96(n0, ka + 8, 0, ivp0, ivn0);
            ap[4 * kc + 3] = ldA96(n1, ka + 8, 0, ivp1, ivn1);
            an[4 * kc]     = ldA96(n0, ka, 32, ivp0, ivn0);
            an[4 * kc + 1] = ldA96(n1, ka, 32, ivp1, ivn1);
            an[4 * kc + 2] = ldA96(n0, ka + 8, 32, ivp0, ivn0);
            an[4 * kc + 3] = ldA96(n1, ka + 8, 32, ivp1, ivn1);
        }
        __syncwarp();
        // re-zero this tile's acc rows + counts for next launch (all values
        // already captured in registers; each tile owns its 16 nodes)
        {
            uint4 z4 = make_uint4(0u, 0u, 0u, 0u);
#pragma unroll
            for (int q = 0; q < 4; q++) {
                int qq = q * 32 + lane;       // 0..127
                int row = qq >> 3, col = qq & 7;
                int nz = base + row;
                if (nz < n_nodes) {
                    ((uint4*)g_accP2h)[(size_t)nz * 8 + col] = z4;
                    ((uint4*)g_accN2h)[(size_t)nz * 8 + col] = z4;
                }
            }
            if (lane < 16) {
                int nz = base + lane;
                if (nz < n_nodes) { g_cntp[nz] = 0.f; g_cntn[nz] = 0.f; }
            }
        }

        // ---- loop1 mma: hp (t 0..3 via WpT), hn (t 4..7 via WnT), K = 96
        float c1[8][4];
#pragma unroll
        for (int t = 0; t < 8; t++)
            c1[t][0] = c1[t][1] = c1[t][2] = c1[t][3] = 0.f;
#pragma unroll
        for (int kc = 0; kc < 6; kc++) {
            unsigned b[2];
#pragma unroll
            for (int t = 0; t < 4; t++) {
                ldb(b, WpT, 104, 8 * t, 16 * kc, lane);
                mma16816(c1[t], ap + 4 * kc, b);
            }
#pragma unroll
            for (int t = 0; t < 4; t++) {
                ldb(b, WnT, 104, 8 * t, 16 * kc, lane);
                mma16816(c1[4 + t], an + 4 * kc, b);
            }
        }
#pragma unroll
        for (int t = 0; t < 8; t++) {
            int c32 = 8 * (t & 3) + 2 * gc;
            const float* barr = (t < 4) ? bp2s : bn2s;
            float b0 = barr[c32], b1 = barr[c32 + 1];
            int cz = (t < 4) ? c32 : 32 + c32;
            *(unsigned*)(zs + gr * 72 + cz) =
                packh2(ftanh(c1[t][0] + b0), ftanh(c1[t][1] + b1));
            *(unsigned*)(zs + (gr + 8) * 72 + cz) =
                packh2(ftanh(c1[t][2] + b0), ftanh(c1[t][3] + b1));
        }
        __syncwarp();

        // ---- loop2: z = tanh(z2 @ Ww + bw) ----
        float c2[8][4];
#pragma unroll
        for (int t = 0; t < 8; t++)
            c2[t][0] = c2[t][1] = c2[t][2] = c2[t][3] = 0.f;
        for (int kc = 0; kc < 4; kc++) {
            unsigned a[4], b[2];
            lda(a, zs, 72, 16 * kc, lane);
#pragma unroll
            for (int t = 0; t < 8; t++) {
                ldb(b, WwT, 72, 8 * t, 16 * kc, lane);
                mma16816(c2[t], a, b);
            }
        }
        __syncwarp();
#pragma unroll
        for (int t = 0; t < 8; t++) {
            int col = 8 * t + 2 * gc;
            float z0 = ftanh(c2[t][0] + bws[col]);
            float z1 = ftanh(c2[t][1] + bws[col + 1]);
            float z2v = ftanh(c2[t][2] + bws[col]);
            float z3 = ftanh(c2[t][3] + bws[col + 1]);
            if (v0) *(float2*)(outz + (size_t)nr0 * 64 + col) = make_float2(z0, z1);
            if (v1) *(float2*)(outz + (size_t)nr1 * 64 + col) = make_float2(z2v, z3);
            *(unsigned*)(zs + gr * 72 + col) = packh2(z0, z1);
            *(unsigned*)(zs + (gr + 8) * 72 + col) = packh2(z2v, z3);
        }
        __syncwarp();

        // ---- loop3: h = relu(bn1(z @ Wm1)) ----
#pragma unroll
        for (int t = 0; t < 8; t++)
            c2[t][0] = c2[t][1] = c2[t][2] = c2[t][3] = 0.f;
        for (int kc = 0; kc < 4; kc++) {
            unsigned a[4], b[2];
            lda(a, zs, 72, 16 * kc, lane);
#pragma unroll
            for (int t = 0; t < 8; t++) {
                ldb(b, W1T, 72, 8 * t, 16 * kc, lane);
                mma16816(c2[t], a, b);
            }
        }
        __syncwarp();
#pragma unroll
        for (int t = 0; t < 8; t++) {
            int col = 8 * t + 2 * gc;
            float h0 = fmaxf(c2[t][0] * sc1[col] + of1[col], 0.f);
            float h1 = fmaxf(c2[t][1] * sc1[col + 1] + of1[col + 1], 0.f);
            float h2 = fmaxf(c2[t][2] * sc1[col] + of1[col], 0.f);
            float h3 = fmaxf(c2[t][3] * sc1[col + 1] + of1[col + 1], 0.f);
            *(unsigned*)(zs + gr * 72 + col) = packh2(h0, h1);
            *(unsigned*)(zs + (gr + 8) * 72 + col) = packh2(h2, h3);
        }
        __syncwarp();

        // ---- loop4: r = relu(bn2(h @ Wm2)); prob = sigmoid(r.w3 + b3) ----
#pragma unroll
        for (int t = 0; t < 8; t++)
            c2[t][0] = c2[t][1] = c2[t][2] = c2[t][3] = 0.f;
        for (int kc = 0; kc < 4; kc++) {
            unsigned a[4], b[2];
            lda(a, zs, 72, 16 * kc, lane);
#pragma unroll
            for (int t = 0; t < 8; t++) {
                ldb(b, W2T, 72, 8 * t, 16 * kc, lane);
                mma16816(c2[t], a, b);
            }
        }
        float p0 = 0.f, p1 = 0.f;
#pragma unroll
        for (int t = 0; t < 8; t++) {
            int col = 8 * t + 2 * gc;
            float r0 = fmaxf(c2[t][0] * sc2[col] + of2[col], 0.f);
            float r1 = fmaxf(c2[t][1] * sc2[col + 1] + of2[col + 1], 0.f);
            float r2 = fmaxf(c2[t][2] * sc2[col] + of2[col], 0.f);
            float r3 = fmaxf(c2[t][3] * sc2[col + 1] + of2[col + 1], 0.f);
            p0 += r0 * w3s[col] + r1 * w3s[col + 1];
            p1 += r2 * w3s[col] + r3 * w3s[col + 1];
        }
        p0 += __shfl_xor_sync(0xffffffffu, p0, 1);
        p0 += __shfl_xor_sync(0xffffffffu, p0, 2);
        p1 += __shfl_xor_sync(0xffffffffu, p1, 1);
        p1 += __shfl_xor_sync(0xffffffffu, p1, 2);
        if ((lane & 3) == 0) {
            float b3 = fb[448];
            if (v0) outp[nr0] = __fdividef(1.0f, 1.0f + __expf(-(p0 + b3)));
            if (v1) outp[nr1] = __fdividef(1.0f, 1.0f + __expf(-(p1 + b3)));
        }
        __syncwarp();
    }
}

// -------------------------------- launcher ----------------------------------
extern "C" void kernel_launch(void* const* d_in, const int* in_sizes, int n_in,
                              void* d_out, int out_size) {
    const float* x   = (const float*)d_in[0];
    const int*   ei  = (const int*)d_in[1];
    const float* Wp1 = (const float*)d_in[2];
    const float* bp1 = (const float*)d_in[3];
    const float* Wn1 = (const float*)d_in[4];
    const float* bn1 = (const float*)d_in[5];
    const float* Wp2 = (const float*)d_in[6];
    const float* bp2 = (const float*)d_in[7];
    const float* Wn2 = (const float*)d_in[8];
    const float* bn2 = (const float*)d_in[9];
    const float* Ww  = (const float*)d_in[10];
    const float* bw  = (const float*)d_in[11];
    const float* Wm1 = (const float*)d_in[12];
    const float* bm1 = (const float*)d_in[13];
    const float* g1  = (const float*)d_in[14];
    const float* be1 = (const float*)d_in[15];
    const float* rm1 = (const float*)d_in[16];
    const float* rv1 = (const float*)d_in[17];
    const float* Wm2 = (const float*)d_in[18];
    const float* bm2 = (const float*)d_in[19];
    const float* g2  = (const float*)d_in[20];
    const float* be2 = (const float*)d_in[21];
    const float* rm2 = (const float*)d_in[22];
    const float* rv2 = (const float*)d_in[23];
    const float* Wm3 = (const float*)d_in[24];
    const float* bm3 = (const float*)d_in[25];

    int Nn = in_sizes[0] / DD;
    int E  = in_sizes[1] / 3;

    float* out  = (float*)d_out;
    float* outz = out;
    float* outp = out + (size_t)Nn * DD;

    int n_tiles = (Nn + 15) / 16;
    int max_blks = (n_tiles + 7) / 8;
    int n_blks1 = max_blks < 296 ? max_blks : 296;
    int n_blks2 = max_blks < 296 ? max_blks : 296;
    int npairs  = (E + 1) / 2;

    const int NODE2_SMEM = 29696 * 2 + 452 * 4;  // 61200 B
    cudaFuncSetAttribute(k_node2TC, cudaFuncAttributeMaxDynamicSharedMemorySize,
                         NODE2_SMEM);

    k_initproj<<<n_blks1, 256>>>(x, Wp1, bp1, Wn1, bn1, ei, E, Nn, n_tiles);

    long t1 = (long)npairs * 4;
    k_edge1<<<(int)((t1 + 255) / 256), 256>>>(npairs, E);

    long tn = (long)Nn * 8;
    k_node1e<<<(int)((tn + 255) / 256), 256>>>(tn);

    long t2 = (long)npairs * 8;
    k_edge2<<<(int)((t2 + 255) / 256), 256>>>(npairs, E);

    k_node2TC<<<n_blks2, 256, NODE2_SMEM>>>(
        Wp2, bp2, Wn2, bn2, Ww, bw,
        Wm1, bm1, g1, be1, rm1, rv1,
        Wm2, bm2, g2, be2, rm2, rv2,
        Wm3, bm3, outz, outp, Nn, n_tiles);
}

// round 17
// speedup vs baseline: 1.0641x; 1.0641x over previous
#include <cuda_runtime.h>
#include <cuda_fp16.h>
#include <math.h>

#define NMAX 100000
#define EMAX 1310720
#define DD 64

// -------- persistent scratch (device globals; no allocation allowed) --------
__device__ __align__(16) __half g_Ph[NMAX * 32];     // x @ Wp1[:64]
__device__ __align__(16) __half g_Qh[NMAX * 32];     // x @ Wn1[:64]
__device__ __align__(16) __half g_RSh[NMAX * 64];    // [x@Wp1[64:]+bp1 | x@Wn1[64:]+bn1]
__device__ __align__(16) __half g_accPh[NMAX * 32];
__device__ __align__(16) __half g_accNh[NMAX * 32];
__device__ __align__(16) __half g_xpnh[NMAX * 64];   // [xp | xn]
__device__ __align__(16) __half g_accP2h[NMAX * 64]; // pos: [sum xp | sum xn] = [A|C]
__device__ __align__(16) __half g_accN2h[NMAX * 64]; // neg: [sum xn | sum xp] = [B|D]
__device__ __align__(16) float  g_cntp[NMAX];        // zeroed at END of node2TC
__device__ __align__(16) float  g_cntn[NMAX];
__device__ __align__(16) int2   g_es[EMAX];          // {src, dst or ~dst(neg)}

// ------------------------------ tiny helpers --------------------------------
__device__ __forceinline__ void red_v4h(__half* p, uint4 v) {
    asm volatile("red.global.add.noftz.v4.f16x2 [%0], {%1,%2,%3,%4};"
                 :: "l"(p), "r"(v.x), "r"(v.y), "r"(v.z), "r"(v.w)
                 : "memory");
}
__device__ __forceinline__ unsigned packh2(float a, float b) {
    __half2 h = __floats2half2_rn(a, b);
    return *(unsigned*)&h;
}
__device__ __forceinline__ void h8tof(uint4 v, float* o) {
    const __half2* h = (const __half2*)&v;
#pragma unroll
    for (int j = 0; j < 4; j++) {
        float2 f = __half22float2(h[j]);
        o[2 * j] = f.x;
        o[2 * j + 1] = f.y;
    }
}
// fast tanh: 1 - 2/(exp(2x)+1); inf-safe at both ends, rel err ~1e-6
__device__ __forceinline__ float ftanh(float x) {
    float e = __expf(2.0f * x);
    return 1.0f - __fdividef(2.0f, e + 1.0f);
}

// ---------------- mma.m16n8k16 f16 -> f32, analytic fragments ---------------
__device__ __forceinline__ void mma16816(float* c, const unsigned* a, const unsigned* b) {
    asm volatile(
        "mma.sync.aligned.m16n8k16.row.col.f32.f16.f16.f32 "
        "{%0,%1,%2,%3}, {%4,%5,%6,%7}, {%8,%9}, {%0,%1,%2,%3};"
        : "+f"(c[0]), "+f"(c[1]), "+f"(c[2]), "+f"(c[3])
        : "r"(a[0]), "r"(a[1]), "r"(a[2]), "r"(a[3]), "r"(b[0]), "r"(b[1]));
}
__device__ __forceinline__ void lda(unsigned* a, const __half* base, int stride,
                                    int k0, int lane) {
    int gr = lane >> 2, gc = lane & 3;
    const __half* p = base + gr * stride + k0 + 2 * gc;
    a[0] = *(const unsigned*)p;
    a[1] = *(const unsigned*)(p + 8 * stride);
    a[2] = *(const unsigned*)(p + 8);
    a[3] = *(const unsigned*)(p + 8 * stride + 8);
}
__device__ __forceinline__ void ldb(unsigned* b, const __half* WT, int stride,
                                    int n0, int k0, int lane) {
    int gn = lane >> 2, gc = lane & 3;
    const __half* p = WT + (n0 + gn) * stride + k0 + 2 * gc;
    b[0] = *(const unsigned*)p;
    b[1] = *(const unsigned*)(p + 8);
}
// loop1 A-operand element pair straight from gmem (see R12 comments)
__device__ __forceinline__ unsigned ldA96(int n, int ka, int off,
                                          __half2 ivp, __half2 ivn) {
    __half2 v;
    if (ka < 32) {
        v = *(const __half2*)(g_accP2h + (size_t)n * 64 + off + ka);
        v = __hmul2(v, ivp);
    } else if (ka < 64) {
        v = *(const __half2*)(g_accN2h + (size_t)n * 64 + off + (ka - 32));
        v = __hmul2(v, ivn);
    } else {
        v = *(const __half2*)(g_xpnh + (size_t)n * 64 + off + (ka - 64));
    }
    return *(unsigned*)&v;
}

// ---------- fused init + projection: ONE wave, every block does both --------
// each of the (exactly-resident) blocks runs the proj grid-stride loop, then
// the zero+pack grid-stride loop. Removes the two-wave serialization measured
// in R13's profile (96 regs -> 2 blocks/SM -> only 296 blocks resident).
__global__ void __launch_bounds__(256)
k_initproj(const float* __restrict__ x,
           const float* __restrict__ Wp1, const float* __restrict__ bp1,
           const float* __restrict__ Wn1, const float* __restrict__ bn1,
           const int* __restrict__ ei, int E, int n_nodes, int n_tiles) {
    __shared__ __align__(16) __half WT[128 * 72];
    __shared__ float b1s[64];
    int tid = threadIdx.x;
    for (int i = tid; i < 64 * 128; i += 256) {
        int k = i >> 7, col = i & 127;
        float w;
        if (col < 32)       w = Wp1[k * 32 + col];
        else if (col < 64)  w = Wn1[k * 32 + (col - 32)];
        else if (col < 96)  w = Wp1[(64 + k) * 32 + (col - 64)];
        else                w = Wn1[(64 + k) * 32 + (col - 96)];
        WT[col * 72 + k] = __float2half(w);
    }
    if (tid < 32) { b1s[tid] = bp1[tid]; b1s[32 + tid] = bn1[tid]; }
    __syncthreads();

    int wid = tid >> 5, lane = tid & 31;
    int gr = lane >> 2, gc = lane & 3;
    int tile_stride = gridDim.x * 8;

    // ---------------- phase A: projection GEMM, grid-stride tiles -----------
    for (int tile = blockIdx.x * 8 + wid; tile < n_tiles; tile += tile_stride) {
        int base = tile * 16;
        int r0 = base + gr, r1 = base + gr + 8;
        bool v0 = r0 < n_nodes, v1 = r1 < n_nodes;
        size_t rr0 = v0 ? (size_t)r0 : 0, rr1 = v1 ? (size_t)r1 : 0;

        unsigned af[16];
#pragma unroll
        for (int kc = 0; kc < 4; kc++) {
            const float* p0 = x + rr0 * 64 + 16 * kc + 2 * gc;
            const float* p1 = x + rr1 * 64 + 16 * kc + 2 * gc;
            float2 f0 = *(const float2*)p0;
            float2 f1 = *(const float2*)p1;
            float2 f2 = *(const float2*)(p0 + 8);
            float2 f3 = *(const float2*)(p1 + 8);
            af[4 * kc]     = packh2(f0.x, f0.y);
            af[4 * kc + 1] = packh2(f1.x, f1.y);
            af[4 * kc + 2] = packh2(f2.x, f2.y);
            af[4 * kc + 3] = packh2(f3.x, f3.y);
        }

        float c[16][4];
#pragma unroll
        for (int t = 0; t < 16; t++)
            c[t][0] = c[t][1] = c[t][2] = c[t][3] = 0.f;
#pragma unroll
        for (int kc = 0; kc < 4; kc++) {
#pragma unroll
            for (int t = 0; t < 16; t++) {
                unsigned b[2];
                ldb(b, WT, 72, 8 * t, 16 * kc, lane);
                mma16816(c[t], af + 4 * kc, b);
            }
        }
#pragma unroll
        for (int t = 0; t < 16; t++) {
            int colw = 8 * t + 2 * gc;
            if (colw < 64) {
                __half* dstb = (colw < 32) ? g_Ph : g_Qh;
                int cw = colw & 31;
                if (v0) *(unsigned*)(dstb + rr0 * 32 + cw) = packh2(c[t][0], c[t][1]);
                if (v1) *(unsigned*)(dstb + rr1 * 32 + cw) = packh2(c[t][2], c[t][3]);
            } else {
                float bb0 = b1s[colw - 64], bb1 = b1s[colw - 63];
                if (v0) *(unsigned*)(g_RSh + rr0 * 64 + (colw - 64)) =
                    packh2(c[t][0] + bb0, c[t][1] + bb1);
                if (v1) *(unsigned*)(g_RSh + rr1 * 64 + (colw - 64)) =
                    packh2(c[t][2] + bb0, c[t][3] + bb1);
            }
        }
    }

    // ---------------- phase B: zero accumulators + pack edges ---------------
    {
        int i = blockIdx.x * 256 + tid;
        int stride = gridDim.x * 256;
        uint4 z4 = make_uint4(0u, 0u, 0u, 0u);
        int nh = n_nodes * 4;
        for (int j = i; j < nh; j += stride) {
            ((uint4*)g_accPh)[j] = z4;
            ((uint4*)g_accNh)[j] = z4;
        }
        int nd = n_nodes * 8;
        for (int j = i; j < nd; j += stride) {
            ((uint4*)g_accP2h)[j] = z4;
            ((uint4*)g_accN2h)[j] = z4;
        }
        for (int e = i; e < E; e += stride) {
            long eb = 3L * e;
            int s  = __ldg(ei + eb);
            int d  = __ldg(ei + eb + 1);
            int sg = __ldg(ei + eb + 2);
            bool pos = (sg > 0);
            g_es[e] = make_int2(s, pos ? d : ~d);
            atomicAdd(pos ? (g_cntp + d) : (g_cntn + d), 1.0f);
        }
    }
}

// --------------------------- layer-1 aggregation ----------------------------
// 2 edges per thread; 4 chunk-threads per edge pair. (counts done in init)
__global__ void k_edge1(int npairs, int E) {
    long idx = (long)blockIdx.x * blockDim.x + threadIdx.x;
    int p = (int)(idx >> 2);
    if (p >= npairs) return;
    int c = (int)(idx & 3);
    int4 es = __ldg((const int4*)g_es + p);
    bool has1 = (2 * p + 1 < E);

    int s0 = es.x, d0 = es.y;
    bool pos0 = (d0 >= 0);
    if (!pos0) d0 = ~d0;
    int s1 = es.z, d1 = es.w;
    bool pos1 = (d1 >= 0);
    if (!pos1) d1 = ~d1;

    uint4 v0 = *((const uint4*)(pos0 ? g_Ph : g_Qh) + (size_t)s0 * 4 + c);
    uint4 v1;
    if (has1) v1 = *((const uint4*)(pos1 ? g_Ph : g_Qh) + (size_t)s1 * 4 + c);

    red_v4h((pos0 ? g_accPh : g_accNh) + (size_t)d0 * 32 + c * 8, v0);
    if (has1)
        red_v4h((pos1 ? g_accPh : g_accNh) + (size_t)d1 * 32 + c * 8, v1);
}

// --------------------- node layer 1: elementwise tanh -----------------------
__global__ void k_node1e(long total) {
    long idx = (long)blockIdx.x * blockDim.x + threadIdx.x;
    if (idx >= total) return;
    int n = (int)(idx >> 3);
    int c = (int)(idx & 7);
    uint4 rs = ((const uint4*)g_RSh)[idx];
    uint4 acc;
    float inv;
    if (c < 4) {
        acc = ((const uint4*)g_accPh)[(size_t)n * 4 + c];
        inv = 1.0f / fmaxf(g_cntp[n], 1.0f);
    } else {
        acc = ((const uint4*)g_accNh)[(size_t)n * 4 + (c - 4)];
        inv = 1.0f / fmaxf(g_cntn[n], 1.0f);
    }
    float rf[8], af[8];
    h8tof(rs, rf);
    h8tof(acc, af);
    uint4 o;
    unsigned* ou = (unsigned*)&o;
#pragma unroll
    for (int j = 0; j < 4; j++)
        ou[j] = packh2(ftanh(rf[2 * j] + af[2 * j] * inv),
                       ftanh(rf[2 * j + 1] + af[2 * j + 1] * inv));
    ((uint4*)g_xpnh)[idx] = o;
}

// --------------------------- layer-2 aggregation ----------------------------
// 2 edges per thread; 8 chunk-threads per edge pair.
__global__ void k_edge2(int npairs, int E) {
    long idx = (long)blockIdx.x * blockDim.x + threadIdx.x;
    int p = (int)(idx >> 3);
    if (p >= npairs) return;
    int c = (int)(idx & 7);
    int4 es = __ldg((const int4*)g_es + p);
    bool has1 = (2 * p + 1 < E);

    int s0 = es.x, d0 = es.y;
    int s1 = es.z, d1 = es.w;

    uint4 v0 = *((const uint4*)g_xpnh + (size_t)s0 * 8 + c);
    uint4 v1;
    if (has1) v1 = *((const uint4*)g_xpnh + (size_t)s1 * 8 + c);

    if (d0 >= 0) {
        red_v4h(g_accP2h + (size_t)d0 * 64 + c * 8, v0);
    } else {
        red_v4h(g_accN2h + (size_t)(~d0) * 64 + (((c + 4) & 7)) * 8, v0);
    }
    if (has1) {
        if (d1 >= 0) {
            red_v4h(g_accP2h + (size_t)d1 * 64 + c * 8, v1);
        } else {
            red_v4h(g_accN2h + (size_t)(~d1) * 64 + (((c + 4) & 7)) * 8, v1);
        }
    }
}

// ------------- node layer 2 + MLP head: tensor-core warp tiles --------------
// grid-stride over tiles; loop1 A-operands fully register-prefetched from gmem.
// counts re-zeroed after use (R12-identical).
__global__ void __launch_bounds__(256, 2)
k_node2TC(const float* __restrict__ Wp2, const float* __restrict__ bp2,
          const float* __restrict__ Wn2, const float* __restrict__ bn2,
          const float* __restrict__ Ww,  const float* __restrict__ bw,
          const float* __restrict__ Wm1, const float* __restrict__ bm1,
          const float* __restrict__ g1,  const float* __restrict__ be1,
          const float* __restrict__ rm1, const float* __restrict__ rv1,
          const float* __restrict__ Wm2, const float* __restrict__ bm2,
          const float* __restrict__ g2,  const float* __restrict__ be2,
          const float* __restrict__ rm2, const float* __restrict__ rv2,
          const float* __restrict__ Wm3, const float* __restrict__ bm3,
          float* __restrict__ outz, float* __restrict__ outp,
          int n_nodes, int n_tiles) {
    extern __shared__ __align__(16) __half smh[];
    __half* WpT = smh;                    // 32 x 104
    __half* WnT = smh + 3328;             // 32 x 104
    __half* WwT = smh + 6656;             // 64 x 72
    __half* W1T = smh + 11264;            // 64 x 72
    __half* W2T = smh + 15872;            // 64 x 72
    float* fb = (float*)(smh + 29696);
    float* bp2s = fb;         // 32
    float* bn2s = fb + 32;    // 32
    float* bws  = fb + 64;    // 64
    float* sc1  = fb + 128;   // 64
    float* of1  = fb + 192;   // 64
    float* sc2  = fb + 256;   // 64
    float* of2  = fb + 320;   // 64
    float* w3s  = fb + 384;   // 64
    // fb[448] = b3

    int tid = threadIdx.x;
    for (int i = tid; i < 96 * 32; i += 256) {
        int k = i >> 5, nn = i & 31;
        WpT[nn * 104 + k] = __float2half(Wp2[i]);
        WnT[nn * 104 + k] = __float2half(Wn2[i]);
    }
    for (int i = tid; i < 64 * 64; i += 256) {
        int k = i >> 6, nn = i & 63;
        WwT[nn * 72 + k] = __float2half(Ww[i]);
        W1T[nn * 72 + k] = __float2half(Wm1[i]);
        W2T[nn * 72 + k] = __float2half(Wm2[i]);
    }
    if (tid < 32) { bp2s[tid] = bp2[tid]; bn2s[tid] = bn2[tid]; }
    if (tid < 64) {
        bws[tid] = bw[tid];
        float s1 = g1[tid] * rsqrtf(rv1[tid] + 1e-5f);
        sc1[tid] = s1;
        of1[tid] = (bm1[tid] - rm1[tid]) * s1 + be1[tid];
        float s2 = g2[tid] * rsqrtf(rv2[tid] + 1e-5f);
        sc2[tid] = s2;
        of2[tid] = (bm2[tid] - rm2[tid]) * s2 + be2[tid];
        w3s[tid] = Wm3[tid];
    }
    if (tid == 0) fb[448] = bm3[0];
    __syncthreads();

    int wid = tid >> 5, lane = tid & 31;
    __half* zs = smh + 20480 + wid * 1152;  // 16 x 72
    int gr = lane >> 2, gc = lane & 3;
    int tile_stride = gridDim.x * 8;

    for (int tile = blockIdx.x * 8 + wid; tile < n_tiles; tile += tile_stride) {
        int base = tile * 16;
        int nr0 = base + gr, nr1 = base + gr + 8;
        bool v0 = nr0 < n_nodes, v1 = nr1 < n_nodes;
        int n0 = v0 ? nr0 : (n_nodes - 1);
        int n1 = v1 ? nr1 : (n_nodes - 1);

        __half2 ivp0 = __float2half2_rn(1.0f / fmaxf(g_cntp[n0], 1.0f));
        __half2 ivn0 = __float2half2_rn(1.0f / fmaxf(g_cntn[n0], 1.0f));
        __half2 ivp1 = __float2half2_rn(1.0f / fmaxf(g_cntp[n1], 1.0f));
        __half2 ivn1 = __float2half2_rn(1.0f / fmaxf(g_cntn[n1], 1.0f));
        __syncwarp();
        // re-zero counts for next launch (each valid node owned by exactly
        // one tile; padding reads of a just-zeroed count only produce values
        // discarded by the v0/v1 store guards)
        if (lane < 16) {
            int nz = base + lane;
            if (nz < n_nodes) { g_cntp[nz] = 0.f; g_cntn[nz] = 0.f; }
        }

        // ---- loop1 prefetch: ALL 48 A-fragment words issued before any mma
        unsigned ap[24], an[24];
#pragma unroll
        for (int kc = 0; kc < 6; kc++) {
            int ka = 16 * kc + 2 * gc;
            ap[4 * kc]     = ldA96(n0, ka, 0, ivp0, ivn0);
            ap[4 * kc + 1] = ldA96(n1, ka, 0, ivp1, ivn1);
            ap[4 * kc + 2] = ldA96(n0, ka + 8, 0, ivp0, ivn0);
            ap[4 * kc + 3] = ldA96(n1, ka + 8, 0, ivp1, ivn1);
            an[4 * kc]     = ldA96(n0, ka, 32, ivp0, ivn0);
            an[4 * kc + 1] = ldA96(n1, ka, 32, ivp1, ivn1);
            an[4 * kc + 2] = ldA96(n0, ka + 8, 32, ivp0, ivn0);
            an[4 * kc + 3] = ldA96(n1, ka + 8, 32, ivp1, ivn1);
        }

        // ---- loop1 mma: hp (t 0..3 via WpT), hn (t 4..7 via WnT), K = 96
        float c1[8][4];
#pragma unroll
        for (int t = 0; t < 8; t++)
            c1[t][0] = c1[t][1] = c1[t][2] = c1[t][3] = 0.f;
#pragma unroll
        for (int kc = 0; kc < 6; kc++) {
            unsigned b[2];
#pragma unroll
            for (int t = 0; t < 4; t++) {
                ldb(b, WpT, 104, 8 * t, 16 * kc, lane);
                mma16816(c1[t], ap + 4 * kc, b);
            }
#pragma unroll
            for (int t = 0; t < 4; t++) {
                ldb(b, WnT, 104, 8 * t, 16 * kc, lane);
                mma16816(c1[4 + t], an + 4 * kc, b);
            }
        }
#pragma unroll
        for (int t = 0; t < 8; t++) {
            int c32 = 8 * (t & 3) + 2 * gc;
            const float* barr = (t < 4) ? bp2s : bn2s;
            float b0 = barr[c32], b1 = barr[c32 + 1];
            int cz = (t < 4) ? c32 : 32 + c32;
            *(unsigned*)(zs + gr * 72 + cz) =
                packh2(ftanh(c1[t][0] + b0), ftanh(c1[t][1] + b1));
            *(unsigned*)(zs + (gr + 8) * 72 + cz) =
                packh2(ftanh(c1[t][2] + b0), ftanh(c1[t][3] + b1));
        }
        __syncwarp();

        // ---- loop2: z = tanh(z2 @ Ww + bw) ----
        float c2[8][4];
#pragma unroll
        for (int t = 0; t < 8; t++)
            c2[t][0] = c2[t][1] = c2[t][2] = c2[t][3] = 0.f;
        for (int kc = 0; kc < 4; kc++) {
            unsigned a[4], b[2];
            lda(a, zs, 72, 16 * kc, lane);
#pragma unroll
            for (int t = 0; t < 8; t++) {
                ldb(b, WwT, 72, 8 * t, 16 * kc, lane);
                mma16816(c2[t], a, b);
            }
        }
        __syncwarp();
#pragma unroll
        for (int t = 0; t < 8; t++) {
            int col = 8 * t + 2 * gc;
            float z0 = ftanh(c2[t][0] + bws[col]);
            float z1 = ftanh(c2[t][1] + bws[col + 1]);
            float z2v = ftanh(c2[t][2] + bws[col]);
            float z3 = ftanh(c2[t][3] + bws[col + 1]);
            if (v0) *(float2*)(outz + (size_t)nr0 * 64 + col) = make_float2(z0, z1);
            if (v1) *(float2*)(outz + (size_t)nr1 * 64 + col) = make_float2(z2v, z3);
            *(unsigned*)(zs + gr * 72 + col) = packh2(z0, z1);
            *(unsigned*)(zs + (gr + 8) * 72 + col) = packh2(z2v, z3);
        }
        __syncwarp();

        // ---- loop3: h = relu(bn1(z @ Wm1)) ----
#pragma unroll
        for (int t = 0; t < 8; t++)
            c2[t][0] = c2[t][1] = c2[t][2] = c2[t][3] = 0.f;
        for (int kc = 0; kc < 4; kc++) {
            unsigned a[4], b[2];
            lda(a, zs, 72, 16 * kc, lane);
#pragma unroll
            for (int t = 0; t < 8; t++) {
                ldb(b, W1T, 72, 8 * t, 16 * kc, lane);
                mma16816(c2[t], a, b);
            }
        }
        __syncwarp();
#pragma unroll
        for (int t = 0; t < 8; t++) {
            int col = 8 * t + 2 * gc;
            float h0 = fmaxf(c2[t][0] * sc1[col] + of1[col], 0.f);
            float h1 = fmaxf(c2[t][1] * sc1[col + 1] + of1[col + 1], 0.f);
            float h2 = fmaxf(c2[t][2] * sc1[col] + of1[col], 0.f);
            float h3 = fmaxf(c2[t][3] * sc1[col + 1] + of1[col + 1], 0.f);
            *(unsigned*)(zs + gr * 72 + col) = packh2(h0, h1);
            *(unsigned*)(zs + (gr + 8) * 72 + col) = packh2(h2, h3);
        }
        __syncwarp();

        // ---- loop4: r = relu(bn2(h @ Wm2)); prob = sigmoid(r.w3 + b3) ----
#pragma unroll
        for (int t = 0; t < 8; t++)
            c2[t][0] = c2[t][1] = c2[t][2] = c2[t][3] = 0.f;
        for (int kc = 0; kc < 4; kc++) {
            unsigned a[4], b[2];
            lda(a, zs, 72, 16 * kc, lane);
#pragma unroll
            for (int t = 0; t < 8; t++) {
                ldb(b, W2T, 72, 8 * t, 16 * kc, lane);
                mma16816(c2[t], a, b);
            }
        }
        float p0 = 0.f, p1 = 0.f;
#pragma unroll
        for (int t = 0; t < 8; t++) {
            int col = 8 * t + 2 * gc;
            float r0 = fmaxf(c2[t][0] * sc2[col] + of2[col], 0.f);
            float r1 = fmaxf(c2[t][1] * sc2[col + 1] + of2[col + 1], 0.f);
            float r2 = fmaxf(c2[t][2] * sc2[col] + of2[col], 0.f);
            float r3 = fmaxf(c2[t][3] * sc2[col + 1] + of2[col + 1], 0.f);
            p0 += r0 * w3s[col] + r1 * w3s[col + 1];
            p1 += r2 * w3s[col] + r3 * w3s[col + 1];
        }
        p0 += __shfl_xor_sync(0xffffffffu, p0, 1);
        p0 += __shfl_xor_sync(0xffffffffu, p0, 2);
        p1 += __shfl_xor_sync(0xffffffffu, p1, 1);
        p1 += __shfl_xor_sync(0xffffffffu, p1, 2);
        if ((lane & 3) == 0) {
            float b3 = fb[448];
            if (v0) outp[nr0] = __fdividef(1.0f, 1.0f + __expf(-(p0 + b3)));
            if (v1) outp[nr1] = __fdividef(1.0f, 1.0f + __expf(-(p1 + b3)));
        }
        __syncwarp();
    }
}

// -------------------------------- launcher ----------------------------------
extern "C" void kernel_launch(void* const* d_in, const int* in_sizes, int n_in,
                              void* d_out, int out_size) {
    const float* x   = (const float*)d_in[0];
    const int*   ei  = (const int*)d_in[1];
    const float* Wp1 = (const float*)d_in[2];
    const float* bp1 = (const float*)d_in[3];
    const float* Wn1 = (const float*)d_in[4];
    const float* bn1 = (const float*)d_in[5];
    const float* Wp2 = (const float*)d_in[6];
    const float* bp2 = (const float*)d_in[7];
    const float* Wn2 = (const float*)d_in[8];
    const float* bn2 = (const float*)d_in[9];
    const float* Ww  = (const float*)d_in[10];
    const float* bw  = (const float*)d_in[11];
    const float* Wm1 = (const float*)d_in[12];
    const float* bm1 = (const float*)d_in[13];
    const float* g1  = (const float*)d_in[14];
    const float* be1 = (const float*)d_in[15];
    const float* rm1 = (const float*)d_in[16];
    const float* rv1 = (const float*)d_in[17];
    const float* Wm2 = (const float*)d_in[18];
    const float* bm2 = (const float*)d_in[19];
    const float* g2  = (const float*)d_in[20];
    const float* be2 = (const float*)d_in[21];
    const float* rm2 = (const float*)d_in[22];
    const float* rv2 = (const float*)d_in[23];
    const float* Wm3 = (const float*)d_in[24];
    const float* bm3 = (const float*)d_in[25];

    int Nn = in_sizes[0] / DD;
    int E  = in_sizes[1] / 3;

    float* out  = (float*)d_out;
    float* outz = out;
    float* outp = out + (size_t)Nn * DD;

    int n_tiles = (Nn + 15) / 16;
    int max_blks = (n_tiles + 7) / 8;
    int n_blks1 = max_blks < 296 ? max_blks : 296;
    int n_blks2 = max_blks < 296 ? max_blks : 296;
    int npairs  = (E + 1) / 2;

    const int NODE2_SMEM = 29696 * 2 + 452 * 4;  // 61200 B
    cudaFuncSetAttribute(k_node2TC, cudaFuncAttributeMaxDynamicSharedMemorySize,
                         NODE2_SMEM);

    k_initproj<<<n_blks1, 256>>>(x, Wp1, bp1, Wn1, bn1, ei, E, Nn, n_tiles);

    long t1 = (long)npairs * 4;
    k_edge1<<<(int)((t1 + 255) / 256), 256>>>(npairs, E);

    long tn = (long)Nn * 8;
    k_node1e<<<(int)((tn + 255) / 256), 256>>>(tn);

    long t2 = (long)npairs * 8;
    k_edge2<<<(int)((t2 + 255) / 256), 256>>>(npairs, E);

    k_node2TC<<<n_blks2, 256, NODE2_SMEM>>>(
        Wp2, bp2, Wn2, bn2, Ww, bw,
        Wm1, bm1, g1, be1, rm1, rv1,
        Wm2, bm2, g2, be2, rm2, rv2,
        Wm3, bm3, outz, outp, Nn, n_tiles);
}